// round 11
// baseline (speedup 1.0000x reference)
#include <cuda_runtime.h>
#include <mma.h>
#include <cstdint>

using namespace nvcuda;

// ---------------------------------------------------------------------------
// Problem constants
// ---------------------------------------------------------------------------
#define HDIM    128
#define MSGDIM  256
#define GDIM    384
#define MAXROWS 200192      // 200000 rounded up to a multiple of 128 (pad rows)

// Gate pre-activation scratch (device globals: no cudaMalloc allowed)
__device__ float g_gi[(size_t)MAXROWS * GDIM];   // X @ W_ih^T
__device__ float g_gh[(size_t)MAXROWS * GDIM];   // h @ W_hh^T

// ---------------------------------------------------------------------------
// Pass-through copy (float4 grid-stride)
// ---------------------------------------------------------------------------
__global__ void copy_f4(const float4* __restrict__ src, float4* __restrict__ dst,
                        size_t n4) {
    size_t i = (size_t)blockIdx.x * blockDim.x + threadIdx.x;
    size_t stride = (size_t)gridDim.x * blockDim.x;
    for (; i < n4; i += stride) dst[i] = src[i];
}

// ---------------------------------------------------------------------------
// wmma tf32 GEMM:  C[b, j] = sum_k A[row(b), k] * W[j, k]
//   A : [*, K] row-major (optionally gathered through ids)
//   W : [GDIM, K] row-major  (== matrix_b col_major with ldb = K)
//   C : [MAXROWS, GDIM] scratch (g_gi / g_gh via `which`)
// CTA tile 128x128xBK32, 256 threads (8 warps in a 2x4 grid, warp tile 64x32),
// cp.async double-buffered smem.
// ---------------------------------------------------------------------------
#define LDA 36                                // 32 + 4 pad (multiple of 4)
static constexpr int SMEM_FLOATS = 2 * 2 * 128 * LDA;   // A+W, 2 stages
static constexpr int SMEM_BYTES  = SMEM_FLOATS * 4;     // 73728

template<int K>
__global__ void __launch_bounds__(256, 2)
gemm_wmma(const float* __restrict__ A, const int* __restrict__ ids,
          const float* __restrict__ W, int which, int B) {
    extern __shared__ float sm[];
    float* As = sm;                     // [2][128][LDA]
    float* Ws = sm + 2 * 128 * LDA;     // [2][128][LDA]
    float* __restrict__ C = which ? g_gh : g_gi;

    const int t  = threadIdx.x;
    const int rb = blockIdx.x * 128;
    const int cb = blockIdx.y * 128;

    // ---- global->smem mapping: 2 threads per row, 16 floats (4 float4) each
    const int lm = t >> 1;
    const int lk = (t & 1) * 16;

    int arow = rb + lm; if (arow > B - 1) arow = B - 1;   // clamp (pad rows)
    const int asrc = ids ? ids[arow] : arow;
    const float* Ap = A + (size_t)asrc * K + lk;
    const float* Wp = W + (size_t)(cb + lm) * K + lk;     // cb+lm <= 383

    const uint32_t sA = (uint32_t)__cvta_generic_to_shared(As + lm * LDA + lk);
    const uint32_t sW = (uint32_t)__cvta_generic_to_shared(Ws + lm * LDA + lk);
    const uint32_t bufB = 128 * LDA * 4;   // bytes per stage buffer

    // ---- warp tiling: 2x4 warps, each 64 rows x 32 cols
    const int wid = t >> 5;
    const int wm  = wid >> 2;   // 0..1
    const int wn  = wid & 3;    // 0..3

    wmma::fragment<wmma::accumulator, 16, 16, 8, float> acc[4][2];
    #pragma unroll
    for (int mf = 0; mf < 4; mf++)
        #pragma unroll
        for (int nf = 0; nf < 2; nf++)
            wmma::fill_fragment(acc[mf][nf], 0.0f);

    constexpr int S = K / 32;

    auto load_stage = [&](int s) {
        const uint32_t boff = (uint32_t)(s & 1) * bufB;
        const float* ap = Ap + s * 32;
        const float* wp = Wp + s * 32;
        #pragma unroll
        for (int q = 0; q < 4; q++) {
            asm volatile("cp.async.cg.shared.global [%0], [%1], 16;"
                         :: "r"(sA + boff + q * 16), "l"(ap + q * 4));
            asm volatile("cp.async.cg.shared.global [%0], [%1], 16;"
                         :: "r"(sW + boff + q * 16), "l"(wp + q * 4));
        }
        asm volatile("cp.async.commit_group;");
    };

    load_stage(0);

    for (int s = 0; s < S; s++) {
        if (s + 1 < S) {
            load_stage(s + 1);
            asm volatile("cp.async.wait_group 1;");
        } else {
            asm volatile("cp.async.wait_group 0;");
        }
        __syncthreads();

        const float* Ab = As + (s & 1) * 128 * LDA;
        const float* Wb = Ws + (s & 1) * 128 * LDA;

        #pragma unroll
        for (int ks = 0; ks < 4; ks++) {
            wmma::fragment<wmma::matrix_a, 16, 16, 8,
                           wmma::precision::tf32, wmma::row_major> af[4];
            wmma::fragment<wmma::matrix_b, 16, 16, 8,
                           wmma::precision::tf32, wmma::col_major> bf[2];
            #pragma unroll
            for (int mf = 0; mf < 4; mf++) {
                wmma::load_matrix_sync(af[mf], Ab + (wm * 64 + mf * 16) * LDA + ks * 8, LDA);
                #pragma unroll
                for (int e = 0; e < af[mf].num_elements; e++)
                    af[mf].x[e] = wmma::__float_to_tf32(af[mf].x[e]);
            }
            #pragma unroll
            for (int nf = 0; nf < 2; nf++) {
                wmma::load_matrix_sync(bf[nf], Wb + (wn * 32 + nf * 16) * LDA + ks * 8, LDA);
                #pragma unroll
                for (int e = 0; e < bf[nf].num_elements; e++)
                    bf[nf].x[e] = wmma::__float_to_tf32(bf[nf].x[e]);
            }
            #pragma unroll
            for (int mf = 0; mf < 4; mf++)
                #pragma unroll
                for (int nf = 0; nf < 2; nf++)
                    wmma::mma_sync(acc[mf][nf], af[mf], bf[nf], acc[mf][nf]);
        }
        __syncthreads();
    }

    // ---- store (pad rows land in scratch rows [B, MAXROWS), never read)
    #pragma unroll
    for (int mf = 0; mf < 4; mf++) {
        const int row = rb + wm * 64 + mf * 16;
        #pragma unroll
        for (int nf = 0; nf < 2; nf++) {
            const int col = cb + wn * 32 + nf * 16;
            wmma::store_matrix_sync(C + (size_t)row * GDIM + col,
                                    acc[mf][nf], GDIM, wmma::mem_row_major);
        }
    }
}

// ---------------------------------------------------------------------------
// GRU epilogue + scatter. One block per updated node, 128 threads (one per h).
// ---------------------------------------------------------------------------
__global__ void gru_epilogue(const float* __restrict__ memory,
                             const int* __restrict__ ids,
                             const float* __restrict__ ts,
                             const float* __restrict__ b_ih,
                             const float* __restrict__ b_hh,
                             float* __restrict__ out_mem,
                             float* __restrict__ out_lu,
                             int B) {
    int b = blockIdx.x;
    if (b >= B) return;
    int h = threadIdx.x;                 // 0..127
    int node = ids[b];

    const float* gi = g_gi + (size_t)b * GDIM;
    const float* gh = g_gh + (size_t)b * GDIM;

    float i_r = gi[h]       + b_ih[h];
    float i_z = gi[128 + h] + b_ih[128 + h];
    float i_n = gi[256 + h] + b_ih[256 + h];
    float h_r = gh[h]       + b_hh[h];
    float h_z = gh[128 + h] + b_hh[128 + h];
    float h_n = gh[256 + h] + b_hh[256 + h];

    float hprev = memory[(size_t)node * HDIM + h];

    float r = 1.0f / (1.0f + expf(-(i_r + h_r)));
    float z = 1.0f / (1.0f + expf(-(i_z + h_z)));
    float n = tanhf(i_n + r * h_n);
    float hnew = (1.0f - z) * n + z * hprev;

    out_mem[(size_t)node * HDIM + h] = hnew;
    if (h == 0) out_lu[node] = ts[b];
}

// ---------------------------------------------------------------------------
// kernel_launch
// Inputs: 0 memory 1 last_update 2 ids 3 messages 4 ts 5 W_ih 6 W_hh 7 b_ih 8 b_hh
// Output: [memory' | last_update'] f32
// ---------------------------------------------------------------------------
extern "C" void kernel_launch(void* const* d_in, const int* in_sizes, int n_in,
                              void* d_out, int out_size) {
    const float* memory      = (const float*)d_in[0];
    const float* last_update = (const float*)d_in[1];
    const int*   ids         = (const int*)d_in[2];
    const float* messages    = (const float*)d_in[3];
    const float* ts          = (const float*)d_in[4];
    const float* W_ih        = (const float*)d_in[5];
    const float* W_hh        = (const float*)d_in[6];
    const float* b_ih        = (const float*)d_in[7];
    const float* b_hh        = (const float*)d_in[8];

    const int    B      = in_sizes[2];
    const size_t memN   = (size_t)in_sizes[0];
    const size_t nNodes = (size_t)in_sizes[1];

    float* out_mem = (float*)d_out;
    float* out_lu  = (float*)d_out + memN;

    cudaFuncSetAttribute(gemm_wmma<MSGDIM>,
                         cudaFuncAttributeMaxDynamicSharedMemorySize, SMEM_BYTES);
    cudaFuncSetAttribute(gemm_wmma<HDIM>,
                         cudaFuncAttributeMaxDynamicSharedMemorySize, SMEM_BYTES);

    // Phase 0: pass-through copies (updated rows overwritten in phase 2)
    copy_f4<<<2960, 256>>>((const float4*)memory, (float4*)out_mem, memN / 4);
    copy_f4<<<256, 256>>>((const float4*)last_update, (float4*)out_lu, nNodes / 4);

    // Phase 1: gate pre-activations on the tensor pipe (wmma tf32)
    dim3 ggrid((B + 127) / 128, GDIM / 128);
    gemm_wmma<MSGDIM><<<ggrid, 256, SMEM_BYTES>>>(messages, nullptr, W_ih, 0, B);
    gemm_wmma<HDIM>  <<<ggrid, 256, SMEM_BYTES>>>(memory,   ids,     W_hh, 1, B);

    // Phase 2: GRU cell + scatter
    gru_epilogue<<<B, HDIM>>>(memory, ids, ts, b_ih, b_hh, out_mem, out_lu, B);
}